// round 10
// baseline (speedup 1.0000x reference)
#include <cuda_runtime.h>
#include <cuda_fp16.h>
#include <math.h>

#define NV 50000
#define ME 800000
#define EE 64
#define FE 41
#define FV 92
#define NL 3
#define CC 169      // 2*E + Fe
#define FC0 128
#define FC1 64
#define NG 256
#define EPSB 1e-5f

typedef unsigned long long ull;
typedef unsigned int uint;

// ---------------- scratch (device globals; no allocation allowed) ----------------
__device__ float g_tmp[NV * EE];                  // pre-BN embedding
__device__ float g_v[NV * EE];                    // node state
__device__ float g_A[4L * NV * EE];               // Am | Bm | As | Bs node projections (fp32)
__device__ __half g_h[(size_t)ME * 128];          // pre-BN h in dst-sorted order, interleaved (hm,hs)
__device__ float g_agg[NV * EE];                  // segment-sum target
__device__ float g_stats[256];                    // edge stats: sum_m[64] sum_s[64] sq_m[64] sq_s[64]
__device__ float g_stats2[128];                   // node/embed stats: sum[64] sq[64]
__device__ int g_cntN[NV];                        // per-dst edge count
__device__ int g_rowptr[NV];                      // exclusive prefix (segment starts)
__device__ int g_off[NV];                         // running offsets for rank assignment
__device__ int g_ord[ME];                         // sorted position -> edge id
__device__ float g_pool[NG * EE];
__device__ float g_cnt[NG];
__device__ float g_r0[NG * EE];
__device__ float g_r1[NG * FC0];
__device__ float g_r2[NG * FC1];

__device__ __forceinline__ float sigmoidf_(float x) { return 1.f / (1.f + __expf(-x)); }
__device__ __forceinline__ float softplusf_(float x) {
    return fmaxf(x, 0.f) + log1pf(__expf(-fabsf(x)));
}
__device__ __forceinline__ ull pack2_(float lo, float hi) {
    ull u;
    asm("mov.b64 %0,{%1,%2};" : "=l"(u) : "f"(lo), "f"(hi));
    return u;
}
__device__ __forceinline__ void ffma2_(ull& acc, ull a, ull b) {
    asm("fma.rn.f32x2 %0, %1, %2, %0;" : "+l"(acc) : "l"(a), "l"(b));
}
__device__ __forceinline__ float unpack_sum_(ull acc) {
    float lo, hi;
    asm("mov.b64 {%0,%1},%2;" : "=f"(lo), "=f"(hi) : "l"(acc));
    return lo + hi;
}

// ---------------- init: zero pool/cnt + embed stats + histogram bins ----------------
__global__ void k_init() {
    int i = blockIdx.x * blockDim.x + threadIdx.x;
    int stride = gridDim.x * blockDim.x;
    for (int j = i; j < NG * EE; j += stride) g_pool[j] = 0.f;
    for (int j = i; j < NG; j += stride) g_cnt[j] = 0.f;
    for (int j = i; j < 128; j += stride) g_stats2[j] = 0.f;
    for (int j = i; j < NV; j += stride) g_cntN[j] = 0;
}

// ---------------- dst histogram (one-time) ----------------
__global__ void k_hist(const int* __restrict__ dst) {
    for (int e = blockIdx.x * blockDim.x + threadIdx.x; e < ME; e += gridDim.x * blockDim.x)
        atomicAdd(&g_cntN[__ldg(dst + e)], 1);
}

// ---------------- exclusive scan over 50k counts (one-time, single block) ----------------
__global__ void k_scan() {
    __shared__ int spart[1024];
    int t = threadIdx.x;
    const int CH = (NV + 1023) / 1024;   // 49
    int lo = t * CH, hi = min(lo + CH, NV);
    int s = 0;
    for (int i = lo; i < hi; i++) s += g_cntN[i];
    spart[t] = s;
    __syncthreads();
    for (int off = 1; off < 1024; off <<= 1) {
        int v = (t >= off) ? spart[t - off] : 0;
        __syncthreads();
        spart[t] += v;
        __syncthreads();
    }
    int run = spart[t] - s;  // exclusive prefix of this chunk
    for (int i = lo; i < hi; i++) {
        int c = g_cntN[i];
        g_rowptr[i] = run;
        g_off[i] = run;
        run += c;
    }
}

// ---------------- rank assignment: ord[p] = e (one-time) ----------------
__global__ void k_rank(const int* __restrict__ dst) {
    for (int e = blockIdx.x * blockDim.x + threadIdx.x; e < ME; e += gridDim.x * blockDim.x) {
        int p = atomicAdd(&g_off[__ldg(dst + e)], 1);
        g_ord[p] = e;
    }
}

// ---------------- embedding GEMM + stats (f32x2 K-packed, dual acc) ----------------
__global__ void k_embed(const float* __restrict__ nf, const float* __restrict__ W,
                        const float* __restrict__ b) {
    int tid = threadIdx.x;                 // 256
    int c = tid & 63, ry = tid >> 6;
    ull w2[FV / 2];                        // 46 pairs
#pragma unroll
    for (int k2 = 0; k2 < FV / 2; k2++)
        w2[k2] = pack2_(W[(2 * k2) * EE + c], W[(2 * k2 + 1) * EE + c]);
    float bias = b[c];
    __shared__ __align__(16) float snf[4 * FV];
    __shared__ float sred[256];
    float s1 = 0.f, s2 = 0.f;
    for (int row0 = blockIdx.x * 4; row0 < NV; row0 += gridDim.x * 4) {
        __syncthreads();
        for (int i = tid; i < 4 * FV; i += 256) snf[i] = nf[(size_t)row0 * FV + i];
        __syncthreads();
        const ull* vp = reinterpret_cast<const ull*>(&snf[ry * FV]);
        ull acc0 = pack2_(bias, 0.f), acc1 = 0ULL;
#pragma unroll
        for (int k2 = 0; k2 < FV / 2 - 1; k2 += 2) {
            ffma2_(acc0, vp[k2], w2[k2]);
            ffma2_(acc1, vp[k2 + 1], w2[k2 + 1]);
        }
        float v = unpack_sum_(acc0) + unpack_sum_(acc1);
        g_tmp[(row0 + ry) * EE + c] = v;
        s1 += v; s2 += v * v;
    }
    __syncthreads();
    sred[tid] = s1; __syncthreads();
    if (tid < 64) atomicAdd(&g_stats2[tid], sred[tid] + sred[tid + 64] + sred[tid + 128] + sred[tid + 192]);
    __syncthreads();
    sred[tid] = s2; __syncthreads();
    if (tid < 64) atomicAdd(&g_stats2[64 + tid], sred[tid] + sred[tid + 64] + sred[tid + 128] + sred[tid + 192]);
}

// ---------------- embed BN + SiLU (inline finalize) ----------------
__global__ void k_embed_apply(const float* __restrict__ g, const float* __restrict__ be) {
    int i = blockIdx.x * blockDim.x + threadIdx.x;
    if (i >= NV * EE) return;
    int c = i & 63;
    float m = g_stats2[c] * (1.f / NV);
    float r = rsqrtf(g_stats2[64 + c] * (1.f / NV) - m * m + EPSB);
    float x = g_tmp[i];
    float xn = (x - m) * r * g[c] + be[c];
    g_v[i] = xn * sigmoidf_(xn);
}

// ---------------- node projections: A = v @ {Wm_src,Wm_dst,Ws_src,Ws_dst} ----------------
__global__ void k_nodeproj(const float* __restrict__ Wm, const float* __restrict__ Ws, int l) {
    if (blockIdx.x == 0 && threadIdx.x < 256) g_stats[threadIdx.x] = 0.f;  // zero edge stats
    int tid = threadIdx.x;
    int t = tid >> 6, col = tid & 63;
    const float* base = ((t < 2) ? Wm : Ws) + (size_t)l * CC * EE + (size_t)(t & 1) * (64 * EE) + col;
    ull w2[32];
#pragma unroll
    for (int k2 = 0; k2 < 32; k2++)
        w2[k2] = pack2_(base[(size_t)(2 * k2) * EE], base[(size_t)(2 * k2 + 1) * EE]);
    __shared__ __align__(16) float sv[256];
    float* outb = g_A + (size_t)t * NV * EE + col;
    for (int row0 = blockIdx.x * 4; row0 < NV; row0 += gridDim.x * 4) {
        __syncthreads();
        sv[tid] = g_v[row0 * EE + tid];
        __syncthreads();
#pragma unroll
        for (int r = 0; r < 4; r++) {
            const ull* vp = reinterpret_cast<const ull*>(&sv[r * 64]);
            ull acc0 = 0ULL, acc1 = 0ULL;
#pragma unroll
            for (int k2 = 0; k2 < 32; k2 += 2) {
                ffma2_(acc0, vp[k2], w2[k2]);
                ffma2_(acc1, vp[k2 + 1], w2[k2 + 1]);
            }
            outb[(size_t)(row0 + r) * EE] = unpack_sum_(acc0) + unpack_sum_(acc1);
        }
    }
}

// ---------------- fused edge pass 1, DST-SORTED ORDER: inline ef-GEMM + gathers +
//                  BN stats + sequential h(fp16) store ----------------
__global__ void k_edgefused(const float* __restrict__ ef, const int* __restrict__ src,
                            const int* __restrict__ dst, const float* __restrict__ Wm,
                            const float* __restrict__ Ws, const float* __restrict__ bm,
                            const float* __restrict__ bs, int l) {
    int tid = threadIdx.x;   // 128
    if (blockIdx.x == 0) g_stats2[tid] = 0.f;  // zero node stats for k_aggnode
    int c = tid & 63;
    int half = tid >> 6;     // 0 gate, 1 screen
    const float* Wbase = (half ? Ws : Wm) + (size_t)l * CC * EE + (size_t)128 * EE + c;
    ull w2[22];
#pragma unroll
    for (int k2 = 0; k2 < 22; k2++) {
        float w0 = (2 * k2 < FE) ? Wbase[(size_t)(2 * k2) * EE] : 0.f;
        float w1 = (2 * k2 + 1 < FE) ? Wbase[(size_t)(2 * k2 + 1) * EE] : 0.f;
        w2[k2] = pack2_(w0, w1);
    }
    float bias = (half ? bs : bm)[l * EE + c];
    const float* A1 = g_A + (size_t)(2 * half) * NV * EE;       // src table
    const float* A2 = g_A + (size_t)(2 * half + 1) * NV * EE;   // dst table
    __shared__ __align__(16) float sef[4 * 44];
    __shared__ __align__(16) __half sh[4 * 128];
    float s1 = 0.f, s2 = 0.f;
    for (int j0 = blockIdx.x * 4; j0 < ME; j0 += gridDim.x * 4) {
        int e0 = __ldg(&g_ord[j0]),     e1 = __ldg(&g_ord[j0 + 1]);
        int e2 = __ldg(&g_ord[j0 + 2]), e3 = __ldg(&g_ord[j0 + 3]);
        __syncthreads();
        for (int i = tid; i < 4 * FE; i += 128) {
            int r = i / FE, k = i - r * FE;
            int er = (r == 0) ? e0 : (r == 1) ? e1 : (r == 2) ? e2 : e3;
            sef[r * 44 + k] = __ldg(&ef[(size_t)er * FE + k]);
        }
        if (tid < 12) { int r = tid / 3, k = FE + tid % 3; sef[r * 44 + k] = 0.f; }
        __syncthreads();
#pragma unroll
        for (int r = 0; r < 4; r++) {
            int e = (r == 0) ? e0 : (r == 1) ? e1 : (r == 2) ? e2 : e3;
            int s = __ldg(src + e), d = __ldg(dst + e);
            float gsum = A1[s * EE + c] + A2[d * EE + c];
            const ull* ep = reinterpret_cast<const ull*>(&sef[r * 44]);
            ull acc = pack2_(bias, 0.f);
#pragma unroll
            for (int k2 = 0; k2 < 22; k2++) ffma2_(acc, ep[k2], w2[k2]);
            float h = unpack_sum_(acc) + gsum;
            s1 += h; s2 += h * h;
            sh[r * 128 + 2 * c + half] = __float2half_rn(h);
        }
        __syncthreads();
        const uint* shp = reinterpret_cast<const uint*>(sh);
        uint* outp = reinterpret_cast<uint*>(g_h) + (size_t)j0 * 64;
#pragma unroll
        for (int i = tid; i < 256; i += 128) outp[i] = shp[i];
    }
    atomicAdd(&g_stats[tid], s1);
    atomicAdd(&g_stats[128 + tid], s2);
}

// ---------------- pass 2: segmented reduce over dst-sorted h, BN+act, no atomics;
//                  fused node BN stats ----------------
__global__ void __launch_bounds__(256) k_aggnode(
        const float* __restrict__ gm, const float* __restrict__ bem,
        const float* __restrict__ gs, const float* __restrict__ bes, int l) {
    int tid = threadIdx.x;   // 256 = 4 node lanes x 64 cols
    int c = tid & 63, sub = tid >> 6;
    float invM = 1.f / ME;
    float mm = g_stats[c] * invM, ms = g_stats[64 + c] * invM;
    float rm = rsqrtf(g_stats[128 + c] * invM - mm * mm + EPSB);
    float rs = rsqrtf(g_stats[192 + c] * invM - ms * ms + EPSB);
    float gmc = gm[l * EE + c] * rm, bemc = bem[l * EE + c] - mm * gmc;
    float gsc = gs[l * EE + c] * rs, besc = bes[l * EE + c] - ms * gsc;
    const uint* hbuf = reinterpret_cast<const uint*>(g_h);
    float s1 = 0.f, s2 = 0.f;
    int n0 = blockIdx.x * 64;
    for (int n = n0 + sub; n < min(n0 + 64, NV); n += 4) {
        int rsg = __ldg(&g_rowptr[n]);
        int cnt = __ldg(&g_cntN[n]);
        float acc = 0.f;
        for (int j = rsg; j < rsg + cnt; j++) {
            uint p = hbuf[(size_t)j * 64 + c];
            __half2 hp = *reinterpret_cast<__half2*>(&p);
            float hm = __low2float(hp), hs = __high2float(hp);
            acc += sigmoidf_(fmaf(hm, gmc, bemc)) * softplusf_(fmaf(hs, gsc, besc));
        }
        g_agg[n * EE + c] = acc;
        s1 += acc; s2 += acc * acc;
    }
    __shared__ float sred[256];
    sred[tid] = s1; __syncthreads();
    if (tid < 64) atomicAdd(&g_stats2[tid], sred[tid] + sred[tid + 64] + sred[tid + 128] + sred[tid + 192]);
    __syncthreads();
    sred[tid] = s2; __syncthreads();
    if (tid < 64) atomicAdd(&g_stats2[64 + tid], sred[tid] + sred[tid + 64] + sred[tid + 128] + sred[tid + 192]);
}

// ---------------- node update: v = softplus(BN(agg) + v), inline finalize ----------------
__global__ void k_nodeapply(const float* __restrict__ gn, const float* __restrict__ ben, int l) {
    int i = blockIdx.x * blockDim.x + threadIdx.x;
    if (i >= NV * EE) return;
    int c = i & 63;
    float m = g_stats2[c] * (1.f / NV);
    float r = rsqrtf(g_stats2[64 + c] * (1.f / NV) - m * m + EPSB);
    float a = g_agg[i];
    float an = (a - m) * r * gn[l * EE + c] + ben[l * EE + c];
    g_v[i] = softplusf_(an + g_v[i]);
}

// ---------------- graph pooling (graph_ids sorted -> run-length accumulate) ----------------
__global__ void k_pool(const int* __restrict__ gid) {
    __shared__ int sg[256];
    int tid = threadIdx.x;   // 64
    int n0 = blockIdx.x * 256;
    int nmax = min(256, NV - n0);
    for (int i = tid; i < nmax; i += 64) sg[i] = gid[n0 + i];
    __syncthreads();
    int cur = sg[0];
    float acc = 0.f, ccnt = 0.f;
    for (int i = 0; i < nmax; i++) {
        int g = sg[i];
        if (g != cur) {
            atomicAdd(&g_pool[cur * EE + tid], acc);
            if (tid == 0) atomicAdd(&g_cnt[cur], ccnt);
            acc = 0.f; ccnt = 0.f; cur = g;
        }
        acc += g_v[(n0 + i) * EE + tid];
        ccnt += 1.f;
    }
    atomicAdd(&g_pool[cur * EE + tid], acc);
    if (tid == 0) atomicAdd(&g_cnt[cur], ccnt);
}

__global__ void k_meanpool() {
    int i = blockIdx.x * blockDim.x + threadIdx.x;
    if (i < NG * EE) g_r0[i] = g_pool[i] / fmaxf(g_cnt[i >> 6], 1.f);
}

// ---------------- fused FC + BN(batch=256) + SiLU ----------------
template <int CI, int CO>
__global__ void k_fc(const float* __restrict__ in, const float* __restrict__ W,
                     const float* __restrict__ b, const float* __restrict__ gam,
                     const float* __restrict__ bet, float* __restrict__ out) {
    int r = threadIdx.x;   // 256 rows
    int co = blockIdx.x;
    float acc = b[co];
    for (int k = 0; k < CI; k++) acc = fmaf(in[r * CI + k], __ldg(&W[k * CO + co]), acc);
    __shared__ float sred[256];
    sred[r] = acc; __syncthreads();
    for (int s = 128; s > 0; s >>= 1) { if (r < s) sred[r] += sred[r + s]; __syncthreads(); }
    float m = sred[0] / 256.f;
    __syncthreads();
    sred[r] = acc * acc; __syncthreads();
    for (int s = 128; s > 0; s >>= 1) { if (r < s) sred[r] += sred[r + s]; __syncthreads(); }
    float var = sred[0] / 256.f - m * m;
    float rstd = rsqrtf(var + EPSB);
    float y = (acc - m) * rstd * gam[co] + bet[co];
    out[r * CO + co] = y * sigmoidf_(y);
}

__global__ void k_head(const float* __restrict__ Wt, const float* __restrict__ bt,
                       float* __restrict__ out) {
    int r = threadIdx.x;
    float acc = bt[0];
#pragma unroll
    for (int k = 0; k < FC1; k++) acc = fmaf(g_r2[r * FC1 + k], __ldg(&Wt[k]), acc);
    out[r] = acc;
}

// ---------------- launch ----------------
extern "C" void kernel_launch(void* const* d_in, const int* in_sizes, int n_in,
                              void* d_out, int out_size) {
    const float* nf    = (const float*)d_in[0];
    const float* ef    = (const float*)d_in[1];
    const int*   src   = (const int*)d_in[2];
    const int*   dst   = (const int*)d_in[3];
    const int*   gid   = (const int*)d_in[4];
    const float* W_emb = (const float*)d_in[5];
    const float* b_emb = (const float*)d_in[6];
    const float* gg_emb = (const float*)d_in[7];
    const float* be_emb = (const float*)d_in[8];
    const float* Wm  = (const float*)d_in[9];
    const float* bm  = (const float*)d_in[10];
    const float* gm  = (const float*)d_in[11];
    const float* bem = (const float*)d_in[12];
    const float* Ws  = (const float*)d_in[13];
    const float* bs  = (const float*)d_in[14];
    const float* gs  = (const float*)d_in[15];
    const float* bes = (const float*)d_in[16];
    const float* gn  = (const float*)d_in[17];
    const float* ben = (const float*)d_in[18];
    const float* Wf0 = (const float*)d_in[19];
    const float* bf0 = (const float*)d_in[20];
    const float* gf0 = (const float*)d_in[21];
    const float* bef0 = (const float*)d_in[22];
    const float* Wf1 = (const float*)d_in[23];
    const float* bf1 = (const float*)d_in[24];
    const float* gf1 = (const float*)d_in[25];
    const float* bef1 = (const float*)d_in[26];
    const float* Wt  = (const float*)d_in[27];
    const float* bt  = (const float*)d_in[28];
    float* out = (float*)d_out;

    float *pr0, *pr1, *pr2;
    cudaGetSymbolAddress((void**)&pr0, g_r0);
    cudaGetSymbolAddress((void**)&pr1, g_r1);
    cudaGetSymbolAddress((void**)&pr2, g_r2);

    k_init<<<64, 256>>>();
    k_hist<<<512, 256>>>(dst);
    k_scan<<<1, 1024>>>();
    k_rank<<<512, 256>>>(dst);
    k_embed<<<512, 256>>>(nf, W_emb, b_emb);
    k_embed_apply<<<(NV * EE + 255) / 256, 256>>>(gg_emb, be_emb);

    for (int l = 0; l < NL; l++) {
        k_nodeproj<<<1024, 256>>>(Wm, Ws, l);
        k_edgefused<<<2048, 128>>>(ef, src, dst, Wm, Ws, bm, bs, l);
        k_aggnode<<<(NV + 63) / 64, 256>>>(gm, bem, gs, bes, l);
        k_nodeapply<<<(NV * EE + 255) / 256, 256>>>(gn, ben, l);
    }

    k_pool<<<(NV + 255) / 256, 64>>>(gid);
    k_meanpool<<<(NG * EE + 255) / 256, 256>>>();
    k_fc<EE, FC0><<<FC0, NG>>>(pr0, Wf0, bf0, gf0, bef0, pr1);
    k_fc<FC0, FC1><<<FC1, NG>>>(pr1, Wf1, bf1, gf1, bef1, pr2);
    k_head<<<1, NG>>>(Wt, bt, out);
}

// round 12
// speedup vs baseline: 1.3385x; 1.3385x over previous
#include <cuda_runtime.h>
#include <cuda_fp16.h>
#include <math.h>

#define NV 50000
#define ME 800000
#define EE 64
#define FE 41
#define FV 92
#define NL 3
#define CC 169      // 2*E + Fe
#define FC0 128
#define FC1 64
#define NG 256
#define EPSB 1e-5f

typedef unsigned long long ull;
typedef unsigned int uint;

// ---------------- scratch (device globals; no allocation allowed) ----------------
__device__ float g_tmp[NV * EE];                  // pre-BN embedding
__device__ float g_v[NV * EE];                    // node state
__device__ float g_A[4L * NV * EE];               // Am | Bm | As | Bs node projections (fp32)
__device__ __half g_h[(size_t)ME * 128];          // per-edge pre-BN h, interleaved (hm[c],hs[c])
__device__ float g_agg[NV * EE];                  // scatter target
__device__ float g_stats[256];                    // edge stats: sum_m[64] sum_s[64] sq_m[64] sq_s[64]
__device__ float g_stats2[128];                   // node/embed stats: sum[64] sq[64]
__device__ float g_pool[NG * EE];
__device__ float g_cnt[NG];
__device__ float g_r0[NG * EE];
__device__ float g_r1[NG * FC0];
__device__ float g_r2[NG * FC1];

__device__ __forceinline__ float sigmoidf_(float x) { return 1.f / (1.f + __expf(-x)); }
__device__ __forceinline__ float softplusf_(float x) {
    return fmaxf(x, 0.f) + log1pf(__expf(-fabsf(x)));
}
__device__ __forceinline__ ull pack2_(float lo, float hi) {
    ull u;
    asm("mov.b64 %0,{%1,%2};" : "=l"(u) : "f"(lo), "f"(hi));
    return u;
}
__device__ __forceinline__ void ffma2_(ull& acc, ull a, ull b) {
    asm("fma.rn.f32x2 %0, %1, %2, %0;" : "+l"(acc) : "l"(a), "l"(b));
}
__device__ __forceinline__ float unpack_sum_(ull acc) {
    float lo, hi;
    asm("mov.b64 {%0,%1},%2;" : "=f"(lo), "=f"(hi) : "l"(acc));
    return lo + hi;
}

// ---------------- init: zero pool/cnt + embed stats ----------------
__global__ void k_init() {
    int i = blockIdx.x * blockDim.x + threadIdx.x;
    int stride = gridDim.x * blockDim.x;
    for (int j = i; j < NG * EE; j += stride) g_pool[j] = 0.f;
    for (int j = i; j < NG; j += stride) g_cnt[j] = 0.f;
    for (int j = i; j < 128; j += stride) g_stats2[j] = 0.f;
}

// ---------------- embedding GEMM + stats (f32x2 K-packed, dual acc) ----------------
__global__ void k_embed(const float* __restrict__ nf, const float* __restrict__ W,
                        const float* __restrict__ b) {
    int tid = threadIdx.x;                 // 256
    int c = tid & 63, ry = tid >> 6;
    ull w2[FV / 2];                        // 46 pairs
#pragma unroll
    for (int k2 = 0; k2 < FV / 2; k2++)
        w2[k2] = pack2_(W[(2 * k2) * EE + c], W[(2 * k2 + 1) * EE + c]);
    float bias = b[c];
    __shared__ __align__(16) float snf[4 * FV];
    __shared__ float sred[256];
    float s1 = 0.f, s2 = 0.f;
    for (int row0 = blockIdx.x * 4; row0 < NV; row0 += gridDim.x * 4) {
        __syncthreads();
        for (int i = tid; i < 4 * FV; i += 256) snf[i] = nf[(size_t)row0 * FV + i];
        __syncthreads();
        const ull* vp = reinterpret_cast<const ull*>(&snf[ry * FV]);
        ull acc0 = pack2_(bias, 0.f), acc1 = 0ULL;
#pragma unroll
        for (int k2 = 0; k2 < FV / 2 - 1; k2 += 2) {
            ffma2_(acc0, vp[k2], w2[k2]);
            ffma2_(acc1, vp[k2 + 1], w2[k2 + 1]);
        }
        float v = unpack_sum_(acc0) + unpack_sum_(acc1);
        g_tmp[(row0 + ry) * EE + c] = v;
        s1 += v; s2 += v * v;
    }
    __syncthreads();
    sred[tid] = s1; __syncthreads();
    if (tid < 64) atomicAdd(&g_stats2[tid], sred[tid] + sred[tid + 64] + sred[tid + 128] + sred[tid + 192]);
    __syncthreads();
    sred[tid] = s2; __syncthreads();
    if (tid < 64) atomicAdd(&g_stats2[64 + tid], sred[tid] + sred[tid + 64] + sred[tid + 128] + sred[tid + 192]);
}

// ---------------- embed BN + SiLU (inline finalize) ----------------
__global__ void k_embed_apply(const float* __restrict__ g, const float* __restrict__ be) {
    int i = blockIdx.x * blockDim.x + threadIdx.x;
    if (i >= NV * EE) return;
    int c = i & 63;
    float m = g_stats2[c] * (1.f / NV);
    float r = rsqrtf(g_stats2[64 + c] * (1.f / NV) - m * m + EPSB);
    float x = g_tmp[i];
    float xn = (x - m) * r * g[c] + be[c];
    g_v[i] = xn * sigmoidf_(xn);
}

// ---------------- node projections: A = v @ {Wm_src,Wm_dst,Ws_src,Ws_dst} ----------------
__global__ void k_nodeproj(const float* __restrict__ Wm, const float* __restrict__ Ws, int l) {
    if (blockIdx.x == 0 && threadIdx.x < 256) g_stats[threadIdx.x] = 0.f;  // zero edge stats
    int tid = threadIdx.x;
    int t = tid >> 6, col = tid & 63;
    const float* base = ((t < 2) ? Wm : Ws) + (size_t)l * CC * EE + (size_t)(t & 1) * (64 * EE) + col;
    ull w2[32];
#pragma unroll
    for (int k2 = 0; k2 < 32; k2++)
        w2[k2] = pack2_(base[(size_t)(2 * k2) * EE], base[(size_t)(2 * k2 + 1) * EE]);
    __shared__ __align__(16) float sv[256];
    float* outb = g_A + (size_t)t * NV * EE + col;
    for (int row0 = blockIdx.x * 4; row0 < NV; row0 += gridDim.x * 4) {
        __syncthreads();
        sv[tid] = g_v[row0 * EE + tid];
        __syncthreads();
#pragma unroll
        for (int r = 0; r < 4; r++) {
            const ull* vp = reinterpret_cast<const ull*>(&sv[r * 64]);
            ull acc0 = 0ULL, acc1 = 0ULL;
#pragma unroll
            for (int k2 = 0; k2 < 32; k2 += 2) {
                ffma2_(acc0, vp[k2], w2[k2]);
                ffma2_(acc1, vp[k2 + 1], w2[k2 + 1]);
            }
            outb[(size_t)(row0 + r) * EE] = unpack_sum_(acc0) + unpack_sum_(acc1);
        }
    }
}

// ---------------- fused edge pass 1 (R3 layout, 8-edge ILP): inline ef-GEMM + gathers
//                  + BN stats + sequential h(fp16) store ----------------
__global__ void k_edgefused(const float* __restrict__ ef, const int* __restrict__ src,
                            const int* __restrict__ dst, const float* __restrict__ Wm,
                            const float* __restrict__ Ws, const float* __restrict__ bm,
                            const float* __restrict__ bs, int l) {
    int tid = threadIdx.x;   // 128
    // zero agg (consumed by pass 2)
    for (int i = blockIdx.x * 128 + tid; i < NV * EE; i += gridDim.x * 128) g_agg[i] = 0.f;
    int c = tid & 63;
    int half = tid >> 6;     // 0 gate, 1 screen
    const float* Wbase = (half ? Ws : Wm) + (size_t)l * CC * EE + (size_t)128 * EE + c;
    ull w2[22];
#pragma unroll
    for (int k2 = 0; k2 < 22; k2++) {
        float w0 = (2 * k2 < FE) ? Wbase[(size_t)(2 * k2) * EE] : 0.f;
        float w1 = (2 * k2 + 1 < FE) ? Wbase[(size_t)(2 * k2 + 1) * EE] : 0.f;
        w2[k2] = pack2_(w0, w1);
    }
    float bias = (half ? bs : bm)[l * EE + c];
    const float* A1 = g_A + (size_t)(2 * half) * NV * EE;       // src table
    const float* A2 = g_A + (size_t)(2 * half + 1) * NV * EE;   // dst table
    __shared__ __align__(16) float sef[8 * 44];
    __shared__ __align__(16) __half sh[8 * 128];
    float s1 = 0.f, s2 = 0.f;
    for (int e0 = blockIdx.x * 8; e0 < ME; e0 += gridDim.x * 8) {
        __syncthreads();
        for (int i = tid; i < 8 * FE; i += 128) {
            int r = i / FE, k = i - r * FE;
            sef[r * 44 + k] = ef[(size_t)e0 * FE + i];
        }
        if (tid < 24) { int r = tid / 3, k = FE + tid % 3; sef[r * 44 + k] = 0.f; }
        __syncthreads();
#pragma unroll
        for (int r = 0; r < 4; r++) {
            int eA = e0 + r, eB = e0 + r + 4;
            int sA = __ldg(src + eA), dA = __ldg(dst + eA);
            int sB = __ldg(src + eB), dB = __ldg(dst + eB);
            float gA = A1[sA * EE + c] + A2[dA * EE + c];
            float gB = A1[sB * EE + c] + A2[dB * EE + c];
            const ull* epA = reinterpret_cast<const ull*>(&sef[r * 44]);
            const ull* epB = reinterpret_cast<const ull*>(&sef[(r + 4) * 44]);
            ull accA = pack2_(bias, 0.f), accB = pack2_(bias, 0.f);
#pragma unroll
            for (int k2 = 0; k2 < 22; k2++) {
                ffma2_(accA, epA[k2], w2[k2]);
                ffma2_(accB, epB[k2], w2[k2]);
            }
            float hA = unpack_sum_(accA) + gA;
            float hB = unpack_sum_(accB) + gB;
            s1 += hA + hB; s2 += hA * hA + hB * hB;
            sh[r * 128 + 2 * c + half] = __float2half_rn(hA);
            sh[(r + 4) * 128 + 2 * c + half] = __float2half_rn(hB);
        }
        __syncthreads();
        const uint* shp = reinterpret_cast<const uint*>(sh);
        uint* outp = reinterpret_cast<uint*>(g_h) + (size_t)e0 * 64;
#pragma unroll
        for (int i = tid; i < 512; i += 128) outp[i] = shp[i];
    }
    atomicAdd(&g_stats[tid], s1);
    atomicAdd(&g_stats[128 + tid], s2);
}

// ---------------- edge pass 2: BN + sigmoid*softplus, scatter (float2 atomics) ----------
__global__ void __launch_bounds__(256) k_edgeapply(
        const int* __restrict__ dst, const float* __restrict__ gm,
        const float* __restrict__ bem, const float* __restrict__ gs,
        const float* __restrict__ bes, int l) {
    int tid = threadIdx.x;   // 256
    if (blockIdx.x == 0 && tid < 128) g_stats2[tid] = 0.f;  // zero node stats
    int c2 = tid & 31, sub = tid >> 5;      // thread owns cols 2*c2, 2*c2+1; 8 edges per iter
    float invM = 1.f / ME;
    int c0 = 2 * c2, c1 = 2 * c2 + 1;
    float mm0 = g_stats[c0] * invM, mm1 = g_stats[c1] * invM;
    float ms0 = g_stats[64 + c0] * invM, ms1 = g_stats[64 + c1] * invM;
    float rm0 = rsqrtf(g_stats[128 + c0] * invM - mm0 * mm0 + EPSB);
    float rm1 = rsqrtf(g_stats[128 + c1] * invM - mm1 * mm1 + EPSB);
    float rs0 = rsqrtf(g_stats[192 + c0] * invM - ms0 * ms0 + EPSB);
    float rs1 = rsqrtf(g_stats[192 + c1] * invM - ms1 * ms1 + EPSB);
    float gmc0 = gm[l * EE + c0] * rm0, bemc0 = bem[l * EE + c0] - mm0 * gmc0;
    float gmc1 = gm[l * EE + c1] * rm1, bemc1 = bem[l * EE + c1] - mm1 * gmc1;
    float gsc0 = gs[l * EE + c0] * rs0, besc0 = bes[l * EE + c0] - ms0 * gsc0;
    float gsc1 = gs[l * EE + c1] * rs1, besc1 = bes[l * EE + c1] - ms1 * gsc1;
    const ull* hbuf = reinterpret_cast<const ull*>(g_h);
    for (int e = blockIdx.x * 8 + sub; e < ME; e += gridDim.x * 8) {
        int d = __ldg(dst + e);
        ull p = hbuf[(size_t)e * 32 + c2];
        __half2 h0 = *reinterpret_cast<__half2*>(&p);                       // (hm[c0], hs[c0])
        __half2 h1 = *(reinterpret_cast<__half2*>(&p) + 1);                 // (hm[c1], hs[c1])
        float hm0 = __low2float(h0), hs0 = __high2float(h0);
        float hm1 = __low2float(h1), hs1 = __high2float(h1);
        float o0 = sigmoidf_(fmaf(hm0, gmc0, bemc0)) * softplusf_(fmaf(hs0, gsc0, besc0));
        float o1 = sigmoidf_(fmaf(hm1, gmc1, bemc1)) * softplusf_(fmaf(hs1, gsc1, besc1));
        atomicAdd(reinterpret_cast<float2*>(&g_agg[d * EE + c0]), make_float2(o0, o1));
    }
}

// ---------------- node BN stats over N ----------------
__global__ void k_nodestats() {
    int tid = threadIdx.x;
    int c = tid & 63, sub = tid >> 6;
    float s1 = 0.f, s2 = 0.f;
    for (int n = blockIdx.x * 4 + sub; n < NV; n += gridDim.x * 4) {
        float x = g_agg[n * EE + c];
        s1 += x; s2 += x * x;
    }
    __shared__ float sred[256];
    sred[tid] = s1; __syncthreads();
    if (tid < 64) atomicAdd(&g_stats2[tid], sred[tid] + sred[tid + 64] + sred[tid + 128] + sred[tid + 192]);
    __syncthreads();
    sred[tid] = s2; __syncthreads();
    if (tid < 64) atomicAdd(&g_stats2[64 + tid], sred[tid] + sred[tid + 64] + sred[tid + 128] + sred[tid + 192]);
}

// ---------------- node update: v = softplus(BN(agg) + v), inline finalize ----------------
__global__ void k_nodeapply(const float* __restrict__ gn, const float* __restrict__ ben, int l) {
    int i = blockIdx.x * blockDim.x + threadIdx.x;
    if (i >= NV * EE) return;
    int c = i & 63;
    float m = g_stats2[c] * (1.f / NV);
    float r = rsqrtf(g_stats2[64 + c] * (1.f / NV) - m * m + EPSB);
    float a = g_agg[i];
    float an = (a - m) * r * gn[l * EE + c] + ben[l * EE + c];
    g_v[i] = softplusf_(an + g_v[i]);
}

// ---------------- graph pooling (graph_ids sorted -> run-length accumulate) ----------------
__global__ void k_pool(const int* __restrict__ gid) {
    __shared__ int sg[256];
    int tid = threadIdx.x;   // 64
    int n0 = blockIdx.x * 256;
    int nmax = min(256, NV - n0);
    for (int i = tid; i < nmax; i += 64) sg[i] = gid[n0 + i];
    __syncthreads();
    int cur = sg[0];
    float acc = 0.f, ccnt = 0.f;
    for (int i = 0; i < nmax; i++) {
        int g = sg[i];
        if (g != cur) {
            atomicAdd(&g_pool[cur * EE + tid], acc);
            if (tid == 0) atomicAdd(&g_cnt[cur], ccnt);
            acc = 0.f; ccnt = 0.f; cur = g;
        }
        acc += g_v[(n0 + i) * EE + tid];
        ccnt += 1.f;
    }
    atomicAdd(&g_pool[cur * EE + tid], acc);
    if (tid == 0) atomicAdd(&g_cnt[cur], ccnt);
}

__global__ void k_meanpool() {
    int i = blockIdx.x * blockDim.x + threadIdx.x;
    if (i < NG * EE) g_r0[i] = g_pool[i] / fmaxf(g_cnt[i >> 6], 1.f);
}

// ---------------- fused FC + BN(batch=256) + SiLU ----------------
template <int CI, int CO>
__global__ void k_fc(const float* __restrict__ in, const float* __restrict__ W,
                     const float* __restrict__ b, const float* __restrict__ gam,
                     const float* __restrict__ bet, float* __restrict__ out) {
    int r = threadIdx.x;   // 256 rows
    int co = blockIdx.x;
    float acc = b[co];
    for (int k = 0; k < CI; k++) acc = fmaf(in[r * CI + k], __ldg(&W[k * CO + co]), acc);
    __shared__ float sred[256];
    sred[r] = acc; __syncthreads();
    for (int s = 128; s > 0; s >>= 1) { if (r < s) sred[r] += sred[r + s]; __syncthreads(); }
    float m = sred[0] / 256.f;
    __syncthreads();
    sred[r] = acc * acc; __syncthreads();
    for (int s = 128; s > 0; s >>= 1) { if (r < s) sred[r] += sred[r + s]; __syncthreads(); }
    float var = sred[0] / 256.f - m * m;
    float rstd = rsqrtf(var + EPSB);
    float y = (acc - m) * rstd * gam[co] + bet[co];
    out[r * CO + co] = y * sigmoidf_(y);
}

__global__ void k_head(const float* __restrict__ Wt, const float* __restrict__ bt,
                       float* __restrict__ out) {
    int r = threadIdx.x;
    float acc = bt[0];
#pragma unroll
    for (int k = 0; k < FC1; k++) acc = fmaf(g_r2[r * FC1 + k], __ldg(&Wt[k]), acc);
    out[r] = acc;
}

// ---------------- launch ----------------
extern "C" void kernel_launch(void* const* d_in, const int* in_sizes, int n_in,
                              void* d_out, int out_size) {
    const float* nf    = (const float*)d_in[0];
    const float* ef    = (const float*)d_in[1];
    const int*   src   = (const int*)d_in[2];
    const int*   dst   = (const int*)d_in[3];
    const int*   gid   = (const int*)d_in[4];
    const float* W_emb = (const float*)d_in[5];
    const float* b_emb = (const float*)d_in[6];
    const float* gg_emb = (const float*)d_in[7];
    const float* be_emb = (const float*)d_in[8];
    const float* Wm  = (const float*)d_in[9];
    const float* bm  = (const float*)d_in[10];
    const float* gm  = (const float*)d_in[11];
    const float* bem = (const float*)d_in[12];
    const float* Ws  = (const float*)d_in[13];
    const float* bs  = (const float*)d_in[14];
    const float* gs  = (const float*)d_in[15];
    const float* bes = (const float*)d_in[16];
    const float* gn  = (const float*)d_in[17];
    const float* ben = (const float*)d_in[18];
    const float* Wf0 = (const float*)d_in[19];
    const float* bf0 = (const float*)d_in[20];
    const float* gf0 = (const float*)d_in[21];
    const float* bef0 = (const float*)d_in[22];
    const float* Wf1 = (const float*)d_in[23];
    const float* bf1 = (const float*)d_in[24];
    const float* gf1 = (const float*)d_in[25];
    const float* bef1 = (const float*)d_in[26];
    const float* Wt  = (const float*)d_in[27];
    const float* bt  = (const float*)d_in[28];
    float* out = (float*)d_out;

    float *pr0, *pr1, *pr2;
    cudaGetSymbolAddress((void**)&pr0, g_r0);
    cudaGetSymbolAddress((void**)&pr1, g_r1);
    cudaGetSymbolAddress((void**)&pr2, g_r2);

    k_init<<<64, 256>>>();
    k_embed<<<512, 256>>>(nf, W_emb, b_emb);
    k_embed_apply<<<(NV * EE + 255) / 256, 256>>>(gg_emb, be_emb);

    for (int l = 0; l < NL; l++) {
        k_nodeproj<<<1024, 256>>>(Wm, Ws, l);
        k_edgefused<<<2048, 128>>>(ef, src, dst, Wm, Ws, bm, bs, l);
        k_edgeapply<<<2048, 256>>>(dst, gm, bem, gs, bes, l);
        k_nodestats<<<1024, 256>>>();
        k_nodeapply<<<(NV * EE + 255) / 256, 256>>>(gn, ben, l);
    }

    k_pool<<<(NV + 255) / 256, 64>>>(gid);
    k_meanpool<<<(NG * EE + 255) / 256, 256>>>();
    k_fc<EE, FC0><<<FC0, NG>>>(pr0, Wf0, bf0, gf0, bef0, pr1);
    k_fc<FC0, FC1><<<FC1, NG>>>(pr1, Wf1, bf1, gf1, bef1, pr2);
    k_head<<<1, NG>>>(Wt, bt, out);
}

// round 13
// speedup vs baseline: 1.4266x; 1.0658x over previous
#include <cuda_runtime.h>
#include <cuda_fp16.h>
#include <math.h>

#define NV 50000
#define ME 800000
#define EE 64
#define FE 41
#define FV 92
#define NL 3
#define CC 169      // 2*E + Fe
#define FC0 128
#define FC1 64
#define NG 256
#define EPSB 1e-5f

typedef unsigned long long ull;
typedef unsigned int uint;

// ---------------- scratch (device globals; no allocation allowed) ----------------
__device__ float g_tmp[NV * EE];                  // pre-BN embedding
__device__ float g_v[NV * EE];                    // node state
__device__ float g_A[4L * NV * EE];               // Am | Bm | As | Bs node projections (fp32)
__device__ __half g_h[(size_t)ME * 128];          // per-edge pre-BN h, interleaved (hm[c],hs[c])
__device__ float g_agg[NV * EE];                  // scatter target
__device__ float g_stats[256];                    // edge stats: sum_m[64] sum_s[64] sq_m[64] sq_s[64]
__device__ float g_stats2[128];                   // node/embed stats: sum[64] sq[64]
__device__ float g_pool[NG * EE];
__device__ float g_cnt[NG];
__device__ float g_r0[NG * EE];
__device__ float g_r1[NG * FC0];
__device__ float g_r2[NG * FC1];

__device__ __forceinline__ float sigmoidf_(float x) { return 1.f / (1.f + __expf(-x)); }
// fast softplus: __logf is MUFU-based; arg in (1,2] where it's ~1e-6 accurate
__device__ __forceinline__ float softplusf_(float x) {
    return fmaxf(x, 0.f) + __logf(1.f + __expf(-fabsf(x)));
}
__device__ __forceinline__ ull pack2_(float lo, float hi) {
    ull u;
    asm("mov.b64 %0,{%1,%2};" : "=l"(u) : "f"(lo), "f"(hi));
    return u;
}
__device__ __forceinline__ void ffma2_(ull& acc, ull a, ull b) {
    asm("fma.rn.f32x2 %0, %1, %2, %0;" : "+l"(acc) : "l"(a), "l"(b));
}
__device__ __forceinline__ float unpack_sum_(ull acc) {
    float lo, hi;
    asm("mov.b64 {%0,%1},%2;" : "=f"(lo), "=f"(hi) : "l"(acc));
    return lo + hi;
}

// ---------------- init: zero pool/cnt + embed stats ----------------
__global__ void k_init() {
    int i = blockIdx.x * blockDim.x + threadIdx.x;
    int stride = gridDim.x * blockDim.x;
    for (int j = i; j < NG * EE; j += stride) g_pool[j] = 0.f;
    for (int j = i; j < NG; j += stride) g_cnt[j] = 0.f;
    for (int j = i; j < 128; j += stride) g_stats2[j] = 0.f;
}

// ---------------- embedding GEMM + stats (f32x2 K-packed, dual acc) ----------------
__global__ void k_embed(const float* __restrict__ nf, const float* __restrict__ W,
                        const float* __restrict__ b) {
    int tid = threadIdx.x;                 // 256
    int c = tid & 63, ry = tid >> 6;
    ull w2[FV / 2];                        // 46 pairs
#pragma unroll
    for (int k2 = 0; k2 < FV / 2; k2++)
        w2[k2] = pack2_(W[(2 * k2) * EE + c], W[(2 * k2 + 1) * EE + c]);
    float bias = b[c];
    __shared__ __align__(16) float snf[4 * FV];
    __shared__ float sred[256];
    float s1 = 0.f, s2 = 0.f;
    for (int row0 = blockIdx.x * 4; row0 < NV; row0 += gridDim.x * 4) {
        __syncthreads();
        for (int i = tid; i < 4 * FV; i += 256) snf[i] = nf[(size_t)row0 * FV + i];
        __syncthreads();
        const ull* vp = reinterpret_cast<const ull*>(&snf[ry * FV]);
        ull acc0 = pack2_(bias, 0.f), acc1 = 0ULL;
#pragma unroll
        for (int k2 = 0; k2 < FV / 2 - 1; k2 += 2) {
            ffma2_(acc0, vp[k2], w2[k2]);
            ffma2_(acc1, vp[k2 + 1], w2[k2 + 1]);
        }
        float v = unpack_sum_(acc0) + unpack_sum_(acc1);
        g_tmp[(row0 + ry) * EE + c] = v;
        s1 += v; s2 += v * v;
    }
    __syncthreads();
    sred[tid] = s1; __syncthreads();
    if (tid < 64) atomicAdd(&g_stats2[tid], sred[tid] + sred[tid + 64] + sred[tid + 128] + sred[tid + 192]);
    __syncthreads();
    sred[tid] = s2; __syncthreads();
    if (tid < 64) atomicAdd(&g_stats2[64 + tid], sred[tid] + sred[tid + 64] + sred[tid + 128] + sred[tid + 192]);
}

// ---------------- embed BN + SiLU (inline finalize) ----------------
__global__ void k_embed_apply(const float* __restrict__ g, const float* __restrict__ be) {
    int i = blockIdx.x * blockDim.x + threadIdx.x;
    if (i >= NV * EE) return;
    int c = i & 63;
    float m = g_stats2[c] * (1.f / NV);
    float r = rsqrtf(g_stats2[64 + c] * (1.f / NV) - m * m + EPSB);
    float x = g_tmp[i];
    float xn = (x - m) * r * g[c] + be[c];
    g_v[i] = xn * sigmoidf_(xn);
}

// ---------------- node projections: A = v @ {Wm_src,Wm_dst,Ws_src,Ws_dst} ----------------
__global__ void k_nodeproj(const float* __restrict__ Wm, const float* __restrict__ Ws, int l) {
    if (blockIdx.x == 0 && threadIdx.x < 256) g_stats[threadIdx.x] = 0.f;  // zero edge stats
    int tid = threadIdx.x;
    int t = tid >> 6, col = tid & 63;
    const float* base = ((t < 2) ? Wm : Ws) + (size_t)l * CC * EE + (size_t)(t & 1) * (64 * EE) + col;
    ull w2[32];
#pragma unroll
    for (int k2 = 0; k2 < 32; k2++)
        w2[k2] = pack2_(base[(size_t)(2 * k2) * EE], base[(size_t)(2 * k2 + 1) * EE]);
    __shared__ __align__(16) float sv[512];
    float* outb = g_A + (size_t)t * NV * EE + col;
    for (int row0 = blockIdx.x * 8; row0 < NV; row0 += gridDim.x * 8) {
        __syncthreads();
        sv[tid] = g_v[row0 * EE + tid];
        sv[tid + 256] = g_v[row0 * EE + tid + 256];
        __syncthreads();
#pragma unroll
        for (int r = 0; r < 8; r++) {
            const ull* vp = reinterpret_cast<const ull*>(&sv[r * 64]);
            ull acc0 = 0ULL, acc1 = 0ULL;
#pragma unroll
            for (int k2 = 0; k2 < 32; k2 += 2) {
                ffma2_(acc0, vp[k2], w2[k2]);
                ffma2_(acc1, vp[k2 + 1], w2[k2 + 1]);
            }
            outb[(size_t)(row0 + r) * EE] = unpack_sum_(acc0) + unpack_sum_(acc1);
        }
    }
}

// ---------------- fused edge pass 1 (8-edge ILP): inline ef-GEMM + gathers
//                  + BN stats + sequential h(fp16) store ----------------
__global__ void k_edgefused(const float* __restrict__ ef, const int* __restrict__ src,
                            const int* __restrict__ dst, const float* __restrict__ Wm,
                            const float* __restrict__ Ws, const float* __restrict__ bm,
                            const float* __restrict__ bs, int l) {
    int tid = threadIdx.x;   // 128
    // zero agg (consumed by pass 2)
    for (int i = blockIdx.x * 128 + tid; i < NV * EE; i += gridDim.x * 128) g_agg[i] = 0.f;
    int c = tid & 63;
    int half = tid >> 6;     // 0 gate, 1 screen
    const float* Wbase = (half ? Ws : Wm) + (size_t)l * CC * EE + (size_t)128 * EE + c;
    ull w2[22];
#pragma unroll
    for (int k2 = 0; k2 < 22; k2++) {
        float w0 = (2 * k2 < FE) ? Wbase[(size_t)(2 * k2) * EE] : 0.f;
        float w1 = (2 * k2 + 1 < FE) ? Wbase[(size_t)(2 * k2 + 1) * EE] : 0.f;
        w2[k2] = pack2_(w0, w1);
    }
    float bias = (half ? bs : bm)[l * EE + c];
    const float* A1 = g_A + (size_t)(2 * half) * NV * EE;       // src table
    const float* A2 = g_A + (size_t)(2 * half + 1) * NV * EE;   // dst table
    __shared__ __align__(16) float sef[8 * 44];
    __shared__ __align__(16) __half sh[8 * 128];
    float s1 = 0.f, s2 = 0.f;
    for (int e0 = blockIdx.x * 8; e0 < ME; e0 += gridDim.x * 8) {
        __syncthreads();
        for (int i = tid; i < 8 * FE; i += 128) {
            int r = i / FE, k = i - r * FE;
            sef[r * 44 + k] = ef[(size_t)e0 * FE + i];
        }
        if (tid < 24) { int r = tid / 3, k = FE + tid % 3; sef[r * 44 + k] = 0.f; }
        __syncthreads();
#pragma unroll
        for (int r = 0; r < 4; r++) {
            int eA = e0 + r, eB = e0 + r + 4;
            int sA = __ldg(src + eA), dA = __ldg(dst + eA);
            int sB = __ldg(src + eB), dB = __ldg(dst + eB);
            float gA = A1[sA * EE + c] + A2[dA * EE + c];
            float gB = A1[sB * EE + c] + A2[dB * EE + c];
            const ull* epA = reinterpret_cast<const ull*>(&sef[r * 44]);
            const ull* epB = reinterpret_cast<const ull*>(&sef[(r + 4) * 44]);
            ull accA = pack2_(bias, 0.f), accB = pack2_(bias, 0.f);
#pragma unroll
            for (int k2 = 0; k2 < 22; k2++) {
                ffma2_(accA, epA[k2], w2[k2]);
                ffma2_(accB, epB[k2], w2[k2]);
            }
            float hA = unpack_sum_(accA) + gA;
            float hB = unpack_sum_(accB) + gB;
            s1 += hA + hB; s2 += hA * hA + hB * hB;
            sh[r * 128 + 2 * c + half] = __float2half_rn(hA);
            sh[(r + 4) * 128 + 2 * c + half] = __float2half_rn(hB);
        }
        __syncthreads();
        const uint* shp = reinterpret_cast<const uint*>(sh);
        uint* outp = reinterpret_cast<uint*>(g_h) + (size_t)e0 * 64;
#pragma unroll
        for (int i = tid; i < 512; i += 128) outp[i] = shp[i];
    }
    atomicAdd(&g_stats[tid], s1);
    atomicAdd(&g_stats[128 + tid], s2);
}

// ---------------- edge pass 2: BN + sigmoid*softplus, scatter (float2 atomics) ----------
__global__ void __launch_bounds__(256) k_edgeapply(
        const int* __restrict__ dst, const float* __restrict__ gm,
        const float* __restrict__ bem, const float* __restrict__ gs,
        const float* __restrict__ bes, int l) {
    int tid = threadIdx.x;   // 256
    if (blockIdx.x == 0 && tid < 128) g_stats2[tid] = 0.f;  // zero node stats
    int c2 = tid & 31, sub = tid >> 5;      // thread owns cols 2*c2, 2*c2+1; 8 edges per iter
    float invM = 1.f / ME;
    int c0 = 2 * c2, c1 = 2 * c2 + 1;
    float mm0 = g_stats[c0] * invM, mm1 = g_stats[c1] * invM;
    float ms0 = g_stats[64 + c0] * invM, ms1 = g_stats[64 + c1] * invM;
    float rm0 = rsqrtf(g_stats[128 + c0] * invM - mm0 * mm0 + EPSB);
    float rm1 = rsqrtf(g_stats[128 + c1] * invM - mm1 * mm1 + EPSB);
    float rs0 = rsqrtf(g_stats[192 + c0] * invM - ms0 * ms0 + EPSB);
    float rs1 = rsqrtf(g_stats[192 + c1] * invM - ms1 * ms1 + EPSB);
    float gmc0 = gm[l * EE + c0] * rm0, bemc0 = bem[l * EE + c0] - mm0 * gmc0;
    float gmc1 = gm[l * EE + c1] * rm1, bemc1 = bem[l * EE + c1] - mm1 * gmc1;
    float gsc0 = gs[l * EE + c0] * rs0, besc0 = bes[l * EE + c0] - ms0 * gsc0;
    float gsc1 = gs[l * EE + c1] * rs1, besc1 = bes[l * EE + c1] - ms1 * gsc1;
    const ull* hbuf = reinterpret_cast<const ull*>(g_h);
    for (int e = blockIdx.x * 8 + sub; e < ME; e += gridDim.x * 8) {
        int d = __ldg(dst + e);
        ull p = hbuf[(size_t)e * 32 + c2];
        __half2 h0 = *reinterpret_cast<__half2*>(&p);                       // (hm[c0], hs[c0])
        __half2 h1 = *(reinterpret_cast<__half2*>(&p) + 1);                 // (hm[c1], hs[c1])
        float hm0 = __low2float(h0), hs0 = __high2float(h0);
        float hm1 = __low2float(h1), hs1 = __high2float(h1);
        float o0 = sigmoidf_(fmaf(hm0, gmc0, bemc0)) * softplusf_(fmaf(hs0, gsc0, besc0));
        float o1 = sigmoidf_(fmaf(hm1, gmc1, bemc1)) * softplusf_(fmaf(hs1, gsc1, besc1));
        atomicAdd(reinterpret_cast<float2*>(&g_agg[d * EE + c0]), make_float2(o0, o1));
    }
}

// ---------------- node BN stats over N ----------------
__global__ void k_nodestats() {
    int tid = threadIdx.x;
    int c = tid & 63, sub = tid >> 6;
    float s1 = 0.f, s2 = 0.f;
    for (int n = blockIdx.x * 4 + sub; n < NV; n += gridDim.x * 4) {
        float x = g_agg[n * EE + c];
        s1 += x; s2 += x * x;
    }
    __shared__ float sred[256];
    sred[tid] = s1; __syncthreads();
    if (tid < 64) atomicAdd(&g_stats2[tid], sred[tid] + sred[tid + 64] + sred[tid + 128] + sred[tid + 192]);
    __syncthreads();
    sred[tid] = s2; __syncthreads();
    if (tid < 64) atomicAdd(&g_stats2[64 + tid], sred[tid] + sred[tid + 64] + sred[tid + 128] + sred[tid + 192]);
}

// ---------------- node update: v = softplus(BN(agg) + v), inline finalize ----------------
__global__ void k_nodeapply(const float* __restrict__ gn, const float* __restrict__ ben, int l) {
    int i = blockIdx.x * blockDim.x + threadIdx.x;
    if (i >= NV * EE) return;
    int c = i & 63;
    float m = g_stats2[c] * (1.f / NV);
    float r = rsqrtf(g_stats2[64 + c] * (1.f / NV) - m * m + EPSB);
    float a = g_agg[i];
    float an = (a - m) * r * gn[l * EE + c] + ben[l * EE + c];
    g_v[i] = softplusf_(an + g_v[i]);
}

// ---------------- graph pooling (graph_ids sorted -> run-length accumulate) ----------------
__global__ void k_pool(const int* __restrict__ gid) {
    __shared__ int sg[256];
    int tid = threadIdx.x;   // 64
    int n0 = blockIdx.x * 256;
    int nmax = min(256, NV - n0);
    for (int i = tid; i < nmax; i += 64) sg[i] = gid[n0 + i];
    __syncthreads();
    int cur = sg[0];
    float acc = 0.f, ccnt = 0.f;
    for (int i = 0; i < nmax; i++) {
        int g = sg[i];
        if (g != cur) {
            atomicAdd(&g_pool[cur * EE + tid], acc);
            if (tid == 0) atomicAdd(&g_cnt[cur], ccnt);
            acc = 0.f; ccnt = 0.f; cur = g;
        }
        acc += g_v[(n0 + i) * EE + tid];
        ccnt += 1.f;
    }
    atomicAdd(&g_pool[cur * EE + tid], acc);
    if (tid == 0) atomicAdd(&g_cnt[cur], ccnt);
}

__global__ void k_meanpool() {
    int i = blockIdx.x * blockDim.x + threadIdx.x;
    if (i < NG * EE) g_r0[i] = g_pool[i] / fmaxf(g_cnt[i >> 6], 1.f);
}

// ---------------- fused FC + BN(batch=256) + SiLU ----------------
template <int CI, int CO>
__global__ void k_fc(const float* __restrict__ in, const float* __restrict__ W,
                     const float* __restrict__ b, const float* __restrict__ gam,
                     const float* __restrict__ bet, float* __restrict__ out) {
    int r = threadIdx.x;   // 256 rows
    int co = blockIdx.x;
    float acc = b[co];
    for (int k = 0; k < CI; k++) acc = fmaf(in[r * CI + k], __ldg(&W[k * CO + co]), acc);
    __shared__ float sred[256];
    sred[r] = acc; __syncthreads();
    for (int s = 128; s > 0; s >>= 1) { if (r < s) sred[r] += sred[r + s]; __syncthreads(); }
    float m = sred[0] / 256.f;
    __syncthreads();
    sred[r] = acc * acc; __syncthreads();
    for (int s = 128; s > 0; s >>= 1) { if (r < s) sred[r] += sred[r + s]; __syncthreads(); }
    float var = sred[0] / 256.f - m * m;
    float rstd = rsqrtf(var + EPSB);
    float y = (acc - m) * rstd * gam[co] + bet[co];
    out[r * CO + co] = y * sigmoidf_(y);
}

__global__ void k_head(const float* __restrict__ Wt, const float* __restrict__ bt,
                       float* __restrict__ out) {
    int r = threadIdx.x;
    float acc = bt[0];
#pragma unroll
    for (int k = 0; k < FC1; k++) acc = fmaf(g_r2[r * FC1 + k], __ldg(&Wt[k]), acc);
    out[r] = acc;
}

// ---------------- launch ----------------
extern "C" void kernel_launch(void* const* d_in, const int* in_sizes, int n_in,
                              void* d_out, int out_size) {
    const float* nf    = (const float*)d_in[0];
    const float* ef    = (const float*)d_in[1];
    const int*   src   = (const int*)d_in[2];
    const int*   dst   = (const int*)d_in[3];
    const int*   gid   = (const int*)d_in[4];
    const float* W_emb = (const float*)d_in[5];
    const float* b_emb = (const float*)d_in[6];
    const float* gg_emb = (const float*)d_in[7];
    const float* be_emb = (const float*)d_in[8];
    const float* Wm  = (const float*)d_in[9];
    const float* bm  = (const float*)d_in[10];
    const float* gm  = (const float*)d_in[11];
    const float* bem = (const float*)d_in[12];
    const float* Ws  = (const float*)d_in[13];
    const float* bs  = (const float*)d_in[14];
    const float* gs  = (const float*)d_in[15];
    const float* bes = (const float*)d_in[16];
    const float* gn  = (const float*)d_in[17];
    const float* ben = (const float*)d_in[18];
    const float* Wf0 = (const float*)d_in[19];
    const float* bf0 = (const float*)d_in[20];
    const float* gf0 = (const float*)d_in[21];
    const float* bef0 = (const float*)d_in[22];
    const float* Wf1 = (const float*)d_in[23];
    const float* bf1 = (const float*)d_in[24];
    const float* gf1 = (const float*)d_in[25];
    const float* bef1 = (const float*)d_in[26];
    const float* Wt  = (const float*)d_in[27];
    const float* bt  = (const float*)d_in[28];
    float* out = (float*)d_out;

    float *pr0, *pr1, *pr2;
    cudaGetSymbolAddress((void**)&pr0, g_r0);
    cudaGetSymbolAddress((void**)&pr1, g_r1);
    cudaGetSymbolAddress((void**)&pr2, g_r2);

    k_init<<<64, 256>>>();
    k_embed<<<512, 256>>>(nf, W_emb, b_emb);
    k_embed_apply<<<(NV * EE + 255) / 256, 256>>>(gg_emb, be_emb);

    for (int l = 0; l < NL; l++) {
        k_nodeproj<<<1024, 256>>>(Wm, Ws, l);
        k_edgefused<<<2048, 128>>>(ef, src, dst, Wm, Ws, bm, bs, l);
        k_edgeapply<<<2048, 256>>>(dst, gm, bem, gs, bes, l);
        k_nodestats<<<1024, 256>>>();
        k_nodeapply<<<(NV * EE + 255) / 256, 256>>>(gn, ben, l);
    }

    k_pool<<<(NV + 255) / 256, 64>>>(gid);
    k_meanpool<<<(NG * EE + 255) / 256, 256>>>();
    k_fc<EE, FC0><<<FC0, NG>>>(pr0, Wf0, bf0, gf0, bef0, pr1);
    k_fc<FC0, FC1><<<FC1, NG>>>(pr1, Wf1, bf1, gf1, bef1, pr2);
    k_head<<<1, NG>>>(Wt, bt, out);
}